// round 10
// baseline (speedup 1.0000x reference)
#include <cuda_runtime.h>
#include <cstdint>

// ---------------------------------------------------------------------------
// Problem constants
// ---------------------------------------------------------------------------
static const int M_ROWS = 50176;
static const float SCALE = 5.656854249492381f;  // sqrt(32) (reference MULTIPLIES)

// ---------------------------------------------------------------------------
// Scratch (device globals; no runtime allocation allowed)
// ---------------------------------------------------------------------------
__device__ float g_X  [6422528];    // stage input  [M,128]
__device__ float g_X2 [6422528];    // stage-2 input [M,128]
__device__ float g_QKV[19267584];   // [M,384]
__device__ float g_AO [6422528];    // attention out [M,128]
__device__ float g_Z  [6422528];    // post-LN      [M,128]
__device__ float g_H1 [25690112];   // fc1 out      [M,512]
__device__ float g_Y  [6422528];    // block output [M,128]

// ---------------------------------------------------------------------------
// Double-buffered SGEMM: C[M,N] = A[M,K] * B[N,K]^T
//   generic epilogue: (+bias[N]) (+res[M,N])
//   LN epilogue (ln_g != null, requires N==128, gridDim.y==1):
//       v = acc + bias[c] + ln_res[r,c];  C[r,c] = LN_row(v)*ln_g[c] + ln_b[c]
// BM=BN=128, BK=8, 256 threads, 8x8 per thread. M%128==0, N%128==0, K%8==0.
// ---------------------------------------------------------------------------
#define GBM 128
#define GBN 128
#define GBK 8

__global__ __launch_bounds__(256, 2) void gemm_db(
    const float* __restrict__ A, const float* __restrict__ B, float* __restrict__ C,
    int M, int N, int K,
    const float* __restrict__ bias, const float* __restrict__ res,
    const float* __restrict__ ln_g, const float* __restrict__ ln_b,
    const float* __restrict__ ln_res)
{
    __shared__ float As[2][GBK][GBM + 4];
    __shared__ float Bs[2][GBK][GBN + 4];

    const int tid = threadIdx.x;
    const int tx = tid & 15;          // N direction
    const int ty = tid >> 4;          // M direction
    const int row0 = blockIdx.x * GBM;
    const int col0 = blockIdx.y * GBN;

    // global load mapping: 256 threads -> 128 rows x 2 float4 (k 0-3 / 4-7)
    const int lr = tid >> 1;
    const int lk = (tid & 1) * 4;
    const float* Ap = A + (size_t)(row0 + lr) * K + lk;
    const float* Bp = B + (size_t)(col0 + lr) * K + lk;

    // preload tile 0
    {
        float4 va = *(const float4*)Ap;
        float4 vb = *(const float4*)Bp;
        As[0][lk + 0][lr] = va.x; As[0][lk + 1][lr] = va.y;
        As[0][lk + 2][lr] = va.z; As[0][lk + 3][lr] = va.w;
        Bs[0][lk + 0][lr] = vb.x; Bs[0][lk + 1][lr] = vb.y;
        Bs[0][lk + 2][lr] = vb.z; Bs[0][lk + 3][lr] = vb.w;
    }
    __syncthreads();

    float acc[8][8];
#pragma unroll
    for (int i = 0; i < 8; i++)
#pragma unroll
        for (int j = 0; j < 8; j++) acc[i][j] = 0.f;

    const int NT = K >> 3;            // 16 or 64
    for (int kt = 0; kt < NT; kt++) {
        const int cb = kt & 1;
        float4 na, nb;
        if (kt + 1 < NT) {            // issue global prefetch early
            na = *(const float4*)(Ap + (size_t)(kt + 1) * GBK);
            nb = *(const float4*)(Bp + (size_t)(kt + 1) * GBK);
        }

#pragma unroll
        for (int kk = 0; kk < GBK; kk++) {
            float ar[8], br[8];
#pragma unroll
            for (int u = 0; u < 8; u += 4)
                *(float4*)&ar[u] = *(const float4*)&As[cb][kk][ty * 8 + u];
#pragma unroll
            for (int u = 0; u < 8; u += 4)
                *(float4*)&br[u] = *(const float4*)&Bs[cb][kk][tx * 8 + u];
#pragma unroll
            for (int i = 0; i < 8; i++)
#pragma unroll
                for (int j = 0; j < 8; j++)
                    acc[i][j] += ar[i] * br[j];
        }

        if (kt + 1 < NT) {
            const int nbuf = cb ^ 1;
            As[nbuf][lk + 0][lr] = na.x; As[nbuf][lk + 1][lr] = na.y;
            As[nbuf][lk + 2][lr] = na.z; As[nbuf][lk + 3][lr] = na.w;
            Bs[nbuf][lk + 0][lr] = nb.x; Bs[nbuf][lk + 1][lr] = nb.y;
            Bs[nbuf][lk + 2][lr] = nb.z; Bs[nbuf][lk + 3][lr] = nb.w;
            __syncthreads();
        }
    }

    if (ln_g) {
        // Fused residual + LayerNorm epilogue (N == 128, col0 == 0).
        const int c0 = tx * 8;
#pragma unroll
        for (int i = 0; i < 8; i++) {
            const int r = row0 + ty * 8 + i;
            float v[8];
            float4 r0 = *(const float4*)&ln_res[(size_t)r * 128 + c0];
            float4 r1 = *(const float4*)&ln_res[(size_t)r * 128 + c0 + 4];
            v[0] = acc[i][0] + bias[c0 + 0] + r0.x;
            v[1] = acc[i][1] + bias[c0 + 1] + r0.y;
            v[2] = acc[i][2] + bias[c0 + 2] + r0.z;
            v[3] = acc[i][3] + bias[c0 + 3] + r0.w;
            v[4] = acc[i][4] + bias[c0 + 4] + r1.x;
            v[5] = acc[i][5] + bias[c0 + 5] + r1.y;
            v[6] = acc[i][6] + bias[c0 + 6] + r1.z;
            v[7] = acc[i][7] + bias[c0 + 7] + r1.w;
            float s = 0.f, s2 = 0.f;
#pragma unroll
            for (int j = 0; j < 8; j++) { s += v[j]; s2 += v[j] * v[j]; }
#pragma unroll
            for (int o = 8; o > 0; o >>= 1) {   // reduce across the 16 tx lanes
                s  += __shfl_xor_sync(0xffffffffu, s,  o);
                s2 += __shfl_xor_sync(0xffffffffu, s2, o);
            }
            float mu  = s * (1.f / 128.f);
            float var = s2 * (1.f / 128.f) - mu * mu;
            float rs  = rsqrtf(var + 1e-5f);
#pragma unroll
            for (int j = 0; j < 8; j++)
                C[(size_t)r * 128 + c0 + j] = (v[j] - mu) * rs * ln_g[c0 + j] + ln_b[c0 + j];
        }
    } else {
#pragma unroll
        for (int i = 0; i < 8; i++) {
            const int r = row0 + ty * 8 + i;
#pragma unroll
            for (int j = 0; j < 8; j++) {
                const int c = col0 + tx * 8 + j;
                float v = acc[i][j];
                if (bias) v += bias[c];
                if (res)  v += res[(size_t)r * N + c];
                C[(size_t)r * N + c] = v;
            }
        }
    }
}

// ---------------------------------------------------------------------------
// window_partition (block stage): x[1,128,224,224] -> X[1024,49,128]
// smem-tiled: one block per window; reads 7-float runs, writes coalesced.
// ---------------------------------------------------------------------------
__global__ __launch_bounds__(256) void part_block(const float* __restrict__ x,
                                                  float* __restrict__ X)
{
    __shared__ float sm[49][129];
    const int win = blockIdx.x;              // 0..1023
    const int hb = win >> 5, wb = win & 31;
    const int tid = threadIdx.x;

    for (int idx = tid; idx < 6272; idx += 256) {   // 128 ch * 49 tok
        int ch = idx / 49, t = idx - ch * 49;
        int r = t / 7, cc = t - r * 7;
        sm[t][ch] = x[ch * 50176 + (hb * 7 + r) * 224 + wb * 7 + cc];
    }
    __syncthreads();
    float* out = X + (size_t)win * 6272;
    for (int idx = tid; idx < 6272; idx += 256) {
        int t = idx >> 7, ch = idx & 127;
        out[idx] = sm[t][ch];
    }
}

// ---------------------------------------------------------------------------
// Quirky unbind(block) -> CHW -> partition(grid), composed.
// ---------------------------------------------------------------------------
__global__ void b2g(const float* __restrict__ Y, float* __restrict__ X2)
{
    int e = blockIdx.x * 256 + threadIdx.x;
    int ch  = e & 127;
    int tok = (e >> 7) & 1023;
    int win = e >> 17;
    int gi = win / 7, gj = win % 7;
    int rr = tok >> 5, ccg = tok & 31;
    int i = gi * 32 + rr, j = gj * 32 + ccg;
    int flat = i * 28672 + j * 128 + ch;
    int c  = flat / 50176, r1 = flat % 50176;
    int hb = r1 / 1568,    r2 = r1 % 1568;
    int r  = r2 / 224,     r3 = r2 % 224;
    int cc = r3 >> 5,      wb = r3 & 31;
    X2[e] = __ldg(&Y[((hb * 32 + wb) * 49 + r * 7 + cc) * 128 + c]);
}

// ---------------------------------------------------------------------------
// Final: quirky unbind(grid) -> out[1,128,224,224]
// ---------------------------------------------------------------------------
__global__ void finalize_out(const float* __restrict__ Y, float* __restrict__ out)
{
    int e = blockIdx.x * 256 + threadIdx.x;
    int cp = e / 50176, rem = e % 50176;
    int i = rem / 224, j = rem % 224;
    int flat = i * 28672 + j * 128 + cp;
    int c   = flat / 50176, r1 = flat % 50176;
    int gi  = r1 / 7168,    r2 = r1 % 7168;
    int rr  = r2 / 224,     r3 = r2 % 224;
    int ccg = r3 / 7,       gj = r3 % 7;
    out[e] = __ldg(&Y[((gi * 7 + gj) * 1024 + rr * 32 + ccg) * 128 + c]);
}

// ---------------------------------------------------------------------------
// Block attention: N=49, one block per (win, head).
// ---------------------------------------------------------------------------
__global__ __launch_bounds__(64) void attn_block(
    const float* __restrict__ QKV, float* __restrict__ AO,
    const float* __restrict__ tbl)
{
    const int head = blockIdx.x & 3;
    const int win  = blockIdx.x >> 2;
    __shared__ float Ks[49][32];
    __shared__ float Vs[49][32];
    __shared__ float Bs[169];
    const int tid = threadIdx.x;
    const float* base = QKV + (size_t)win * 49 * 384;

    for (int idx = tid; idx < 49 * 32; idx += 64) {
        int j = idx >> 5, d = idx & 31;
        Ks[j][d] = base[j * 384 + 128 + head * 32 + d];
        Vs[j][d] = base[j * 384 + 256 + head * 32 + d];
    }
    for (int idx = tid; idx < 169; idx += 64) Bs[idx] = tbl[idx * 4 + head];
    __syncthreads();

    if (tid < 49) {
        float q[32];
#pragma unroll
        for (int d = 0; d < 32; d++) q[d] = base[tid * 384 + head * 32 + d];
        const int r1 = tid / 7, c1 = tid % 7;
        const int bb = (r1 + 6) * 13 + c1 + 6;

        float s[49];
        float mx = -1e30f;
#pragma unroll 7
        for (int j = 0; j < 49; j++) {
            float a = 0.f;
#pragma unroll
            for (int d = 0; d < 32; d++) a += q[d] * Ks[j][d];
            int r2 = j / 7, c2 = j % 7;
            float v = a * SCALE + Bs[bb - r2 * 13 - c2];
            s[j] = v;
            mx = fmaxf(mx, v);
        }
        float l = 0.f;
        for (int j = 0; j < 49; j++) { float p = __expf(s[j] - mx); s[j] = p; l += p; }
        float inv = 1.f / l;

        float o[32];
#pragma unroll
        for (int d = 0; d < 32; d++) o[d] = 0.f;
        for (int j = 0; j < 49; j++) {
            float p = s[j];
#pragma unroll
            for (int d = 0; d < 32; d++) o[d] += p * Vs[j][d];
        }
        float* outp = AO + ((size_t)win * 49 + tid) * 128 + head * 32;
#pragma unroll
        for (int d = 0; d < 32; d++) outp[d] = o[d] * inv;
    }
}

// ---------------------------------------------------------------------------
// Grid attention: N=1024, flash-style online softmax, 64-key tiles.
// ---------------------------------------------------------------------------
__global__ __launch_bounds__(256) void attn_grid(
    const float* __restrict__ QKV, float* __restrict__ AO,
    const float* __restrict__ tbl)
{
    const int head = blockIdx.x & 3;
    const int win  = blockIdx.x >> 2;
    __shared__ float Ks[64][32];
    __shared__ float Vs[64][32];
    __shared__ float Bs[3969];
    const int tid = threadIdx.x;
    const float* base = QKV + (size_t)win * 1024 * 384;

    for (int idx = tid; idx < 3969; idx += 256) Bs[idx] = tbl[idx * 4 + head];

    const int i = blockIdx.y * 256 + tid;
    float q[32];
#pragma unroll
    for (int d = 0; d < 32; d++) q[d] = base[(size_t)i * 384 + head * 32 + d];
    const int r1 = i >> 5, c1 = i & 31;
    const int bb = (r1 + 31) * 63 + c1 + 31;

    float m = -1e30f, l = 0.f;
    float acc[32];
#pragma unroll
    for (int d = 0; d < 32; d++) acc[d] = 0.f;

    for (int t = 0; t < 16; t++) {
        __syncthreads();
        for (int idx = tid; idx < 64 * 32; idx += 256) {
            int j = idx >> 5, d = idx & 31;
            int jj = t * 64 + j;
            Ks[j][d] = base[(size_t)jj * 384 + 128 + head * 32 + d];
            Vs[j][d] = base[(size_t)jj * 384 + 256 + head * 32 + d];
        }
        __syncthreads();

#pragma unroll 4
        for (int j = 0; j < 64; j++) {
            float s = 0.f;
#pragma unroll
            for (int d = 0; d < 32; d++) s += q[d] * Ks[j][d];
            int jj = t * 64 + j;
            int r2 = jj >> 5, c2 = jj & 31;
            s = s * SCALE + Bs[bb - r2 * 63 - c2];
            if (s > m) {
                float cor = __expf(m - s);
                l *= cor;
#pragma unroll
                for (int d = 0; d < 32; d++) acc[d] *= cor;
                m = s;
            }
            float p = __expf(s - m);
            l += p;
#pragma unroll
            for (int d = 0; d < 32; d++) acc[d] += p * Vs[j][d];
        }
    }

    float inv = 1.f / l;
    float* outp = AO + ((size_t)win * 1024 + i) * 128 + head * 32;
#pragma unroll
    for (int d = 0; d < 32; d++) outp[d] = acc[d] * inv;
}

// ---------------------------------------------------------------------------
// Launch
// ---------------------------------------------------------------------------
extern "C" void kernel_launch(void* const* d_in, const int* in_sizes, int n_in,
                              void* d_out, int out_size)
{
    const float* x       = (const float*)d_in[0];
    const float* b_rel   = (const float*)d_in[1];
    const float* b_qkvw  = (const float*)d_in[2];
    const float* b_projw = (const float*)d_in[3];
    const float* b_projb = (const float*)d_in[4];
    const float* b_lng   = (const float*)d_in[5];
    const float* b_lnb   = (const float*)d_in[6];
    const float* b_fc1w  = (const float*)d_in[7];
    const float* b_fc1b  = (const float*)d_in[8];
    const float* b_fc2w  = (const float*)d_in[9];
    const float* b_fc2b  = (const float*)d_in[10];
    const float* g_rel   = (const float*)d_in[11];
    const float* g_qkvw  = (const float*)d_in[12];
    const float* g_projw = (const float*)d_in[13];
    const float* g_projb = (const float*)d_in[14];
    const float* g_lng   = (const float*)d_in[15];
    const float* g_lnb   = (const float*)d_in[16];
    const float* g_fc1w  = (const float*)d_in[17];
    const float* g_fc1b  = (const float*)d_in[18];
    const float* g_fc2w  = (const float*)d_in[19];
    const float* g_fc2b  = (const float*)d_in[20];

    float *X, *X2, *QKV, *AO, *Z, *H1, *Y;
    cudaGetSymbolAddress((void**)&X,   g_X);
    cudaGetSymbolAddress((void**)&X2,  g_X2);
    cudaGetSymbolAddress((void**)&QKV, g_QKV);
    cudaGetSymbolAddress((void**)&AO,  g_AO);
    cudaGetSymbolAddress((void**)&Z,   g_Z);
    cudaGetSymbolAddress((void**)&H1,  g_H1);
    cudaGetSymbolAddress((void**)&Y,   g_Y);

    const int M = M_ROWS;                 // 50176
    const int EL_BLOCKS = 25088;          // 6422528 / 256

    // ---- Block stage ----
    part_block<<<1024, 256>>>(x, X);
    gemm_db<<<dim3(392, 3), 256>>>(X, b_qkvw, QKV, M, 384, 128,
                                   nullptr, nullptr, nullptr, nullptr, nullptr);
    attn_block<<<4096, 64>>>(QKV, AO, b_rel);
    gemm_db<<<dim3(392, 1), 256>>>(AO, b_projw, Z, M, 128, 128,
                                   b_projb, nullptr, b_lng, b_lnb, X);
    gemm_db<<<dim3(392, 4), 256>>>(Z, b_fc1w, H1, M, 512, 128,
                                   b_fc1b, nullptr, nullptr, nullptr, nullptr);
    gemm_db<<<dim3(392, 1), 256>>>(H1, b_fc2w, Y, M, 128, 512,
                                   b_fc2b, Z, nullptr, nullptr, nullptr);

    // ---- Layout shuffle block -> grid (faithful quirky reshape) ----
    b2g<<<EL_BLOCKS, 256>>>(Y, X2);

    // ---- Grid stage ----
    gemm_db<<<dim3(392, 3), 256>>>(X2, g_qkvw, QKV, M, 384, 128,
                                   nullptr, nullptr, nullptr, nullptr, nullptr);
    attn_grid<<<dim3(196, 4), 256>>>(QKV, AO, g_rel);
    gemm_db<<<dim3(392, 1), 256>>>(AO, g_projw, Z, M, 128, 128,
                                   g_projb, nullptr, g_lng, g_lnb, X2);
    gemm_db<<<dim3(392, 4), 256>>>(Z, g_fc1w, H1, M, 512, 128,
                                   g_fc1b, nullptr, nullptr, nullptr, nullptr);
    gemm_db<<<dim3(392, 1), 256>>>(H1, g_fc2w, Y, M, 128, 512,
                                   g_fc2b, Z, nullptr, nullptr, nullptr);

    // ---- Final quirky unbind -> [1,128,224,224] ----
    finalize_out<<<EL_BLOCKS, 256>>>(Y, (float*)d_out);
}

// round 13
// speedup vs baseline: 1.4392x; 1.4392x over previous
#include <cuda_runtime.h>
#include <cuda_bf16.h>
#include <cstdint>

// ---------------------------------------------------------------------------
// Problem constants
// ---------------------------------------------------------------------------
static const int M_ROWS = 50176;
static const float SCALE = 5.656854249492381f;  // sqrt(32) (reference MULTIPLIES)

// ---------------------------------------------------------------------------
// Scratch (device globals; no runtime allocation allowed)
// ---------------------------------------------------------------------------
__device__ float g_X  [6422528];    // stage input  [M,128]
__device__ float g_X2 [6422528];    // stage-2 input [M,128]
__device__ float g_QKV[19267584];   // [M,384]
__device__ float g_AO [6422528];    // attention out [M,128]
__device__ float g_Z  [6422528];    // post-LN      [M,128]
__device__ float g_H1 [25690112];   // fc1 out      [M,512]
__device__ float g_Y  [6422528];    // block output [M,128]

// ---------------------------------------------------------------------------
// Warp-MMA helpers (sm_80+ baseline: ldmatrix + mma.sync bf16)
// ---------------------------------------------------------------------------
__device__ __forceinline__ uint32_t smem_u32(const void* p) {
    uint32_t a;
    asm("{ .reg .u64 t; cvta.to.shared.u64 t, %1; cvt.u32.u64 %0, t; }"
        : "=r"(a) : "l"(p));
    return a;
}

__device__ __forceinline__ void ldsm_x4(uint32_t& r0, uint32_t& r1,
                                        uint32_t& r2, uint32_t& r3, uint32_t addr) {
    asm volatile("ldmatrix.sync.aligned.m8n8.x4.shared.b16 {%0,%1,%2,%3}, [%4];"
                 : "=r"(r0), "=r"(r1), "=r"(r2), "=r"(r3) : "r"(addr));
}

__device__ __forceinline__ void mma_bf16(float* d, const uint32_t* a, const uint32_t* b) {
    asm volatile(
        "mma.sync.aligned.m16n8k16.row.col.f32.bf16.bf16.f32 "
        "{%0,%1,%2,%3}, {%4,%5,%6,%7}, {%8,%9}, {%0,%1,%2,%3};"
        : "+f"(d[0]), "+f"(d[1]), "+f"(d[2]), "+f"(d[3])
        : "r"(a[0]), "r"(a[1]), "r"(a[2]), "r"(a[3]), "r"(b[0]), "r"(b[1]));
}

// fp32 -> (hi, lo) bf16 split, 4 elems, stored to smem (k-contiguous)
__device__ __forceinline__ void cvt_store4(float4 v, __nv_bfloat16* hi, __nv_bfloat16* lo) {
    __nv_bfloat162 h01, h23, l01, l23;
    h01.x = __float2bfloat16(v.x); h01.y = __float2bfloat16(v.y);
    h23.x = __float2bfloat16(v.z); h23.y = __float2bfloat16(v.w);
    l01.x = __float2bfloat16(v.x - __bfloat162float(h01.x));
    l01.y = __float2bfloat16(v.y - __bfloat162float(h01.y));
    l23.x = __float2bfloat16(v.z - __bfloat162float(h23.x));
    l23.y = __float2bfloat16(v.w - __bfloat162float(h23.y));
    *(__nv_bfloat162*)(hi)     = h01;
    *(__nv_bfloat162*)(hi + 2) = h23;
    *(__nv_bfloat162*)(lo)     = l01;
    *(__nv_bfloat162*)(lo + 2) = l23;
}

// ---------------------------------------------------------------------------
// bf16-split tensor-core GEMM: C[M,N] = A[M,K] * B[N,K]^T (+bias) (+res | LN)
// CTA tile 128x128, 256 threads (8 warps: 2 x 4, warp tile 64x32).
// K chunked by 32 fp32; A,B converted to bf16 hi/lo in smem each chunk.
// D += Ahi*Bhi + Alo*Bhi + Ahi*Blo  (fp32 accumulate, ~2^-17 elem error).
// LN mode (ln_g != null, N==128, gridDim.y==1):
//   v = acc + bias + ln_res;  C = LN_row(v)*ln_g + ln_b   (via smem)
// ---------------------------------------------------------------------------
#define BKF 32
#define SPAD 40                    // padded bf16 row length (80 B, LDSM conflict-free)

__global__ __launch_bounds__(256) void gemm_mma(
    const float* __restrict__ A, const float* __restrict__ B, float* __restrict__ C,
    int N, int K,
    const float* __restrict__ bias, const float* __restrict__ res,
    const float* __restrict__ ln_g, const float* __restrict__ ln_b,
    const float* __restrict__ ln_res)
{
    extern __shared__ char smem_raw[];
    __nv_bfloat16* sAh = (__nv_bfloat16*)(smem_raw);
    __nv_bfloat16* sAl = (__nv_bfloat16*)(smem_raw + 10240);
    __nv_bfloat16* sBh = (__nv_bfloat16*)(smem_raw + 20480);
    __nv_bfloat16* sBl = (__nv_bfloat16*)(smem_raw + 30720);

    const int tid  = threadIdx.x;
    const int lane = tid & 31;
    const int wid  = tid >> 5;
    const int wm   = wid >> 2;          // 0..1  (M)
    const int wn   = wid & 3;           // 0..3  (N)
    const int row0 = blockIdx.x * 128;
    const int col0 = blockIdx.y * 128;

    const uint32_t uAh = smem_u32(sAh), uAl = smem_u32(sAl);
    const uint32_t uBh = smem_u32(sBh), uBl = smem_u32(sBl);

    // ldmatrix per-thread address components
    const int a_row = wm * 64 + (lane & 15);            // + mi*16
    const int a_kb  = (lane >> 4) << 3;                 // + ks*16
    const int b_row = wn * 32 + (lane & 7) + (((lane >> 4) & 1) << 3);  // + np*16
    const int b_kb  = ((lane >> 3) & 1) << 3;           // + ks*16

    // staging map: 256 threads -> 128 rows x 2 halves of 16 floats
    const int sr = tid >> 1;
    const int sk = (tid & 1) * 16;
    const float* Ag = A + (size_t)(row0 + sr) * K + sk;
    const float* Bg = B + (size_t)(col0 + sr) * K + sk;

    float acc[4][4][4];
#pragma unroll
    for (int i = 0; i < 4; i++)
#pragma unroll
        for (int j = 0; j < 4; j++)
#pragma unroll
            for (int q = 0; q < 4; q++) acc[i][j][q] = 0.f;

    float4 fa[4], fb[4];
#pragma unroll
    for (int i = 0; i < 4; i++) {
        fa[i] = *(const float4*)(Ag + i * 4);
        fb[i] = *(const float4*)(Bg + i * 4);
    }

    const int NKC = K >> 5;
    for (int kc = 0; kc < NKC; kc++) {
        // stage current chunk (from registers)
#pragma unroll
        for (int i = 0; i < 4; i++) {
            cvt_store4(fa[i], sAh + sr * SPAD + sk + i * 4, sAl + sr * SPAD + sk + i * 4);
            cvt_store4(fb[i], sBh + sr * SPAD + sk + i * 4, sBl + sr * SPAD + sk + i * 4);
        }
        __syncthreads();

        // prefetch next chunk
        if (kc + 1 < NKC) {
#pragma unroll
            for (int i = 0; i < 4; i++) {
                fa[i] = *(const float4*)(Ag + (size_t)(kc + 1) * BKF + i * 4);
                fb[i] = *(const float4*)(Bg + (size_t)(kc + 1) * BKF + i * 4);
            }
        }

        // MMA over the chunk: 2 k16 steps
#pragma unroll
        for (int ks = 0; ks < 2; ks++) {
            uint32_t bh[4][2], bl[4][2];
#pragma unroll
            for (int np = 0; np < 2; np++) {
                uint32_t off = (uint32_t)((b_row + np * 16) * (SPAD * 2) + (ks * 16 + b_kb) * 2);
                ldsm_x4(bh[2 * np][0], bh[2 * np][1], bh[2 * np + 1][0], bh[2 * np + 1][1], uBh + off);
                ldsm_x4(bl[2 * np][0], bl[2 * np][1], bl[2 * np + 1][0], bl[2 * np + 1][1], uBl + off);
            }
#pragma unroll
            for (int mi = 0; mi < 4; mi++) {
                uint32_t off = (uint32_t)((a_row + mi * 16) * (SPAD * 2) + (ks * 16 + a_kb) * 2);
                uint32_t ah[4], al[4];
                ldsm_x4(ah[0], ah[1], ah[2], ah[3], uAh + off);
                ldsm_x4(al[0], al[1], al[2], al[3], uAl + off);
#pragma unroll
                for (int ni = 0; ni < 4; ni++) {
                    mma_bf16(acc[mi][ni], ah, bh[ni]);
                    mma_bf16(acc[mi][ni], al, bh[ni]);
                    mma_bf16(acc[mi][ni], ah, bl[ni]);
                }
            }
        }
        __syncthreads();
    }

    // ---- Epilogue ----
    const int er = (lane >> 2);          // row within m16
    const int ec = (lane & 3) * 2;       // col within n8

    if (ln_g) {
        // v -> smem [128][130], then per-row LayerNorm
        float* sV = (float*)smem_raw;
#pragma unroll
        for (int mi = 0; mi < 4; mi++) {
#pragma unroll
            for (int ni = 0; ni < 4; ni++) {
                int r = wm * 64 + mi * 16 + er;
                int c = wn * 32 + ni * 8 + ec;
                float2 rr0 = *(const float2*)&ln_res[(size_t)(row0 + r) * 128 + c];
                float2 rr1 = *(const float2*)&ln_res[(size_t)(row0 + r + 8) * 128 + c];
                float2 v0, v1;
                v0.x = acc[mi][ni][0] + bias[c]     + rr0.x;
                v0.y = acc[mi][ni][1] + bias[c + 1] + rr0.y;
                v1.x = acc[mi][ni][2] + bias[c]     + rr1.x;
                v1.y = acc[mi][ni][3] + bias[c + 1] + rr1.y;
                *(float2*)&sV[(r)     * 130 + c] = v0;
                *(float2*)&sV[(r + 8) * 130 + c] = v1;
            }
        }
        __syncthreads();

        const int row  = tid >> 1;
        const int half = tid & 1;
        const float* vr = sV + row * 130 + half * 64;
        float s = 0.f, s2 = 0.f;
#pragma unroll
        for (int q = 0; q < 32; q++) {
            float2 t = *(const float2*)(vr + q * 2);
            s  += t.x + t.y;
            s2 += t.x * t.x + t.y * t.y;
        }
        s  += __shfl_xor_sync(0xffffffffu, s,  1);
        s2 += __shfl_xor_sync(0xffffffffu, s2, 1);
        float mu  = s * (1.f / 128.f);
        float var = s2 * (1.f / 128.f) - mu * mu;
        float rs  = rsqrtf(var + 1e-5f);
        float* outp = C + (size_t)(row0 + row) * 128 + half * 64;
        const float* gg = ln_g + half * 64;
        const float* bb = ln_b + half * 64;
#pragma unroll
        for (int q = 0; q < 64; q++)
            outp[q] = (vr[q] - mu) * rs * gg[q] + bb[q];
    } else {
#pragma unroll
        for (int mi = 0; mi < 4; mi++) {
#pragma unroll
            for (int ni = 0; ni < 4; ni++) {
                int r = row0 + wm * 64 + mi * 16 + er;
                int c = col0 + wn * 32 + ni * 8 + ec;
                float b0 = bias ? bias[c]     : 0.f;
                float b1 = bias ? bias[c + 1] : 0.f;
                float2 v0 = {acc[mi][ni][0] + b0, acc[mi][ni][1] + b1};
                float2 v1 = {acc[mi][ni][2] + b0, acc[mi][ni][3] + b1};
                if (res) {
                    float2 rr0 = *(const float2*)&res[(size_t)r * N + c];
                    float2 rr1 = *(const float2*)&res[(size_t)(r + 8) * N + c];
                    v0.x += rr0.x; v0.y += rr0.y;
                    v1.x += rr1.x; v1.y += rr1.y;
                }
                *(float2*)&C[(size_t)r * N + c]       = v0;
                *(float2*)&C[(size_t)(r + 8) * N + c] = v1;
            }
        }
    }
}

// ---------------------------------------------------------------------------
// window_partition (block stage): x[1,128,224,224] -> X[1024,49,128]
// ---------------------------------------------------------------------------
__global__ __launch_bounds__(256) void part_block(const float* __restrict__ x,
                                                  float* __restrict__ X)
{
    __shared__ float sm[49][129];
    const int win = blockIdx.x;
    const int hb = win >> 5, wb = win & 31;
    const int tid = threadIdx.x;

    for (int idx = tid; idx < 6272; idx += 256) {
        int ch = idx / 49, t = idx - ch * 49;
        int r = t / 7, cc = t - r * 7;
        sm[t][ch] = x[ch * 50176 + (hb * 7 + r) * 224 + wb * 7 + cc];
    }
    __syncthreads();
    float* out = X + (size_t)win * 6272;
    for (int idx = tid; idx < 6272; idx += 256) {
        int t = idx >> 7, ch = idx & 127;
        out[idx] = sm[t][ch];
    }
}

// ---------------------------------------------------------------------------
// Quirky unbind(block) -> CHW -> partition(grid), composed.
// ---------------------------------------------------------------------------
__global__ void b2g(const float* __restrict__ Y, float* __restrict__ X2)
{
    int e = blockIdx.x * 256 + threadIdx.x;
    int ch  = e & 127;
    int tok = (e >> 7) & 1023;
    int win = e >> 17;
    int gi = win / 7, gj = win % 7;
    int rr = tok >> 5, ccg = tok & 31;
    int i = gi * 32 + rr, j = gj * 32 + ccg;
    int flat = i * 28672 + j * 128 + ch;
    int c  = flat / 50176, r1 = flat % 50176;
    int hb = r1 / 1568,    r2 = r1 % 1568;
    int r  = r2 / 224,     r3 = r2 % 224;
    int cc = r3 >> 5,      wb = r3 & 31;
    X2[e] = __ldg(&Y[((hb * 32 + wb) * 49 + r * 7 + cc) * 128 + c]);
}

// ---------------------------------------------------------------------------
// Final: quirky unbind(grid) -> out[1,128,224,224]
// ---------------------------------------------------------------------------
__global__ void finalize_out(const float* __restrict__ Y, float* __restrict__ out)
{
    int e = blockIdx.x * 256 + threadIdx.x;
    int cp = e / 50176, rem = e % 50176;
    int i = rem / 224, j = rem % 224;
    int flat = i * 28672 + j * 128 + cp;
    int c   = flat / 50176, r1 = flat % 50176;
    int gi  = r1 / 7168,    r2 = r1 % 7168;
    int rr  = r2 / 224,     r3 = r2 % 224;
    int ccg = r3 / 7,       gj = r3 % 7;
    out[e] = __ldg(&Y[((gi * 7 + gj) * 1024 + rr * 32 + ccg) * 128 + c]);
}

// ---------------------------------------------------------------------------
// Block attention: N=49, one block per (win, head).
// ---------------------------------------------------------------------------
__global__ __launch_bounds__(64) void attn_block(
    const float* __restrict__ QKV, float* __restrict__ AO,
    const float* __restrict__ tbl)
{
    const int head = blockIdx.x & 3;
    const int win  = blockIdx.x >> 2;
    __shared__ float Ks[49][32];
    __shared__ float Vs[49][32];
    __shared__ float Bs[169];
    const int tid = threadIdx.x;
    const float* base = QKV + (size_t)win * 49 * 384;

    for (int idx = tid; idx < 49 * 32; idx += 64) {
        int j = idx >> 5, d = idx & 31;
        Ks[j][d] = base[j * 384 + 128 + head * 32 + d];
        Vs[j][d] = base[j * 384 + 256 + head * 32 + d];
    }
    for (int idx = tid; idx < 169; idx += 64) Bs[idx] = tbl[idx * 4 + head];
    __syncthreads();

    if (tid < 49) {
        float q[32];
#pragma unroll
        for (int d = 0; d < 32; d++) q[d] = base[tid * 384 + head * 32 + d];
        const int r1 = tid / 7, c1 = tid % 7;
        const int bb = (r1 + 6) * 13 + c1 + 6;

        float s[49];
        float mx = -1e30f;
#pragma unroll 7
        for (int j = 0; j < 49; j++) {
            float a = 0.f;
#pragma unroll
            for (int d = 0; d < 32; d++) a += q[d] * Ks[j][d];
            int r2 = j / 7, c2 = j % 7;
            float v = a * SCALE + Bs[bb - r2 * 13 - c2];
            s[j] = v;
            mx = fmaxf(mx, v);
        }
        float l = 0.f;
        for (int j = 0; j < 49; j++) { float p = __expf(s[j] - mx); s[j] = p; l += p; }
        float inv = 1.f / l;

        float o[32];
#pragma unroll
        for (int d = 0; d < 32; d++) o[d] = 0.f;
        for (int j = 0; j < 49; j++) {
            float p = s[j];
#pragma unroll
            for (int d = 0; d < 32; d++) o[d] += p * Vs[j][d];
        }
        float* outp = AO + ((size_t)win * 49 + tid) * 128 + head * 32;
#pragma unroll
        for (int d = 0; d < 32; d++) outp[d] = o[d] * inv;
    }
}

// ---------------------------------------------------------------------------
// Grid attention: N=1024, flash-style online softmax, 64-key tiles.
// ---------------------------------------------------------------------------
__global__ __launch_bounds__(256) void attn_grid(
    const float* __restrict__ QKV, float* __restrict__ AO,
    const float* __restrict__ tbl)
{
    const int head = blockIdx.x & 3;
    const int win  = blockIdx.x >> 2;
    __shared__ float Ks[64][32];
    __shared__ float Vs[64][32];
    __shared__ float Bs[3969];
    const int tid = threadIdx.x;
    const float* base = QKV + (size_t)win * 1024 * 384;

    for (int idx = tid; idx < 3969; idx += 256) Bs[idx] = tbl[idx * 4 + head];

    const int i = blockIdx.y * 256 + tid;
    float q[32];
#pragma unroll
    for (int d = 0; d < 32; d++) q[d] = base[(size_t)i * 384 + head * 32 + d];
    const int r1 = i >> 5, c1 = i & 31;
    const int bb = (r1 + 31) * 63 + c1 + 31;

    float m = -1e30f, l = 0.f;
    float acc[32];
#pragma unroll
    for (int d = 0; d < 32; d++) acc[d] = 0.f;

    for (int t = 0; t < 16; t++) {
        __syncthreads();
        for (int idx = tid; idx < 64 * 32; idx += 256) {
            int j = idx >> 5, d = idx & 31;
            int jj = t * 64 + j;
            Ks[j][d] = base[(size_t)jj * 384 + 128 + head * 32 + d];
            Vs[j][d] = base[(size_t)jj * 384 + 256 + head * 32 + d];
        }
        __syncthreads();

#pragma unroll 4
        for (int j = 0; j < 64; j++) {
            float s = 0.f;
#pragma unroll
            for (int d = 0; d < 32; d++) s += q[d] * Ks[j][d];
            int jj = t * 64 + j;
            int r2 = jj >> 5, c2 = jj & 31;
            s = s * SCALE + Bs[bb - r2 * 63 - c2];
            if (s > m) {
                float cor = __expf(m - s);
                l *= cor;
#pragma unroll
                for (int d = 0; d < 32; d++) acc[d] *= cor;
                m = s;
            }
            float p = __expf(s - m);
            l += p;
#pragma unroll
            for (int d = 0; d < 32; d++) acc[d] += p * Vs[j][d];
        }
    }

    float inv = 1.f / l;
    float* outp = AO + ((size_t)win * 1024 + i) * 128 + head * 32;
#pragma unroll
    for (int d = 0; d < 32; d++) outp[d] = acc[d] * inv;
}

// ---------------------------------------------------------------------------
// Launch
// ---------------------------------------------------------------------------
extern "C" void kernel_launch(void* const* d_in, const int* in_sizes, int n_in,
                              void* d_out, int out_size)
{
    const float* x       = (const float*)d_in[0];
    const float* b_rel   = (const float*)d_in[1];
    const float* b_qkvw  = (const float*)d_in[2];
    const float* b_projw = (const float*)d_in[3];
    const float* b_projb = (const float*)d_in[4];
    const float* b_lng   = (const float*)d_in[5];
    const float* b_lnb   = (const float*)d_in[6];
    const float* b_fc1w  = (const float*)d_in[7];
    const float* b_fc1b  = (const float*)d_in[8];
    const float* b_fc2w  = (const float*)d_in[9];
    const float* b_fc2b  = (const float*)d_in[10];
    const float* g_rel   = (const float*)d_in[11];
    const float* g_qkvw  = (const float*)d_in[12];
    const float* g_projw = (const float*)d_in[13];
    const float* g_projb = (const float*)d_in[14];
    const float* g_lng   = (const float*)d_in[15];
    const float* g_lnb   = (const float*)d_in[16];
    const float* g_fc1w  = (const float*)d_in[17];
    const float* g_fc1b  = (const float*)d_in[18];
    const float* g_fc2w  = (const float*)d_in[19];
    const float* g_fc2b  = (const float*)d_in[20];

    float *X, *X2, *QKV, *AO, *Z, *H1, *Y;
    cudaGetSymbolAddress((void**)&X,   g_X);
    cudaGetSymbolAddress((void**)&X2,  g_X2);
    cudaGetSymbolAddress((void**)&QKV, g_QKV);
    cudaGetSymbolAddress((void**)&AO,  g_AO);
    cudaGetSymbolAddress((void**)&Z,   g_Z);
    cudaGetSymbolAddress((void**)&H1,  g_H1);
    cudaGetSymbolAddress((void**)&Y,   g_Y);

    const int EL_BLOCKS = 25088;          // 6422528 / 256
    const int SMEM_STD = 40960;           // 4 x 128x40 bf16 arrays
    const int SMEM_LN  = 66560;           // 128x130 fp32 (LN epilogue, superset)

    cudaFuncSetAttribute(gemm_mma, cudaFuncAttributeMaxDynamicSharedMemorySize, SMEM_LN);

    // ---- Block stage ----
    part_block<<<1024, 256>>>(x, X);
    gemm_mma<<<dim3(392, 3), 256, SMEM_STD>>>(X, b_qkvw, QKV, 384, 128,
                                              nullptr, nullptr, nullptr, nullptr, nullptr);
    attn_block<<<4096, 64>>>(QKV, AO, b_rel);
    gemm_mma<<<dim3(392, 1), 256, SMEM_LN>>>(AO, b_projw, Z, 128, 128,
                                             b_projb, nullptr, b_lng, b_lnb, X);
    gemm_mma<<<dim3(392, 4), 256, SMEM_STD>>>(Z, b_fc1w, H1, 512, 128,
                                              b_fc1b, nullptr, nullptr, nullptr, nullptr);
    gemm_mma<<<dim3(392, 1), 256, SMEM_STD>>>(H1, b_fc2w, Y, 128, 512,
                                              b_fc2b, Z, nullptr, nullptr, nullptr);

    // ---- Layout shuffle block -> grid (faithful quirky reshape) ----
    b2g<<<EL_BLOCKS, 256>>>(Y, X2);

    // ---- Grid stage ----
    gemm_mma<<<dim3(392, 3), 256, SMEM_STD>>>(X2, g_qkvw, QKV, 384, 128,
                                              nullptr, nullptr, nullptr, nullptr, nullptr);
    attn_grid<<<dim3(196, 4), 256>>>(QKV, AO, g_rel);
    gemm_mma<<<dim3(392, 1), 256, SMEM_LN>>>(AO, g_projw, Z, 128, 128,
                                             g_projb, nullptr, g_lng, g_lnb, X2);
    gemm_mma<<<dim3(392, 4), 256, SMEM_STD>>>(Z, g_fc1w, H1, 512, 128,
                                              g_fc1b, nullptr, nullptr, nullptr, nullptr);
    gemm_mma<<<dim3(392, 1), 256, SMEM_STD>>>(H1, g_fc2w, Y, 128, 512,
                                              g_fc2b, Z, nullptr, nullptr, nullptr);

    // ---- Final quirky unbind -> [1,128,224,224] ----
    finalize_out<<<EL_BLOCKS, 256>>>(Y, (float*)d_out);
}